// round 1
// baseline (speedup 1.0000x reference)
#include <cuda_runtime.h>
#include <math.h>

#define Bn 8
#define Tn 1024
#define Cn 512
#define Hn 64
#define NREL 50
#define QK_SCALE 0.125f   // 64^-0.5

// scratch for q,k,v projections: [B*T, H] each
__device__ float g_q[Bn * Tn * Hn];
__device__ float g_k[Bn * Tn * Hn];
__device__ float g_v[Bn * Tn * Hn];

// ---------------------------------------------------------------------------
// Kernel 1: QKV projection. grid (128, 3), 256 threads.
// Tile: BM=64, BN=64 (full H), BK=32. 4x4 register micro-tile per thread.
// ---------------------------------------------------------------------------
__global__ __launch_bounds__(256) void qkv_kernel(
    const float* __restrict__ x, const float* __restrict__ Wq,
    const float* __restrict__ Wk, const float* __restrict__ Wv)
{
    __shared__ float As[32][68];   // As[k][m] (transposed)
    __shared__ float Bs[32][68];   // Bs[k][n]
    const int m0 = blockIdx.x * 64;
    const float* W = blockIdx.y == 0 ? Wq : (blockIdx.y == 1 ? Wk : Wv);
    float* out = blockIdx.y == 0 ? g_q : (blockIdx.y == 1 ? g_k : g_v);
    const int tid = threadIdx.x;
    const int tm = (tid >> 4) << 2;   // 0..60
    const int tn = (tid & 15) << 2;   // 0..60

    float acc[4][4];
#pragma unroll
    for (int i = 0; i < 4; i++)
#pragma unroll
        for (int j = 0; j < 4; j++) acc[i][j] = 0.f;

    for (int k0 = 0; k0 < Cn; k0 += 32) {
        // A tile 64x32: coalesced float4 load, transposed scalar store
#pragma unroll
        for (int it = 0; it < 2; it++) {
            int f = it * 256 + tid;
            int r = f >> 3, c = (f & 7) << 2;
            float4 v = *(const float4*)(x + (size_t)(m0 + r) * Cn + k0 + c);
            As[c + 0][r] = v.x; As[c + 1][r] = v.y;
            As[c + 2][r] = v.z; As[c + 3][r] = v.w;
        }
        // B tile 32x64: direct float4 copy
#pragma unroll
        for (int it = 0; it < 2; it++) {
            int f = it * 256 + tid;
            int kr = f >> 4, nc = (f & 15) << 2;
            *(float4*)&Bs[kr][nc] = *(const float4*)(W + (size_t)(k0 + kr) * Hn + nc);
        }
        __syncthreads();
#pragma unroll
        for (int kk = 0; kk < 32; kk++) {
            float4 a4 = *(const float4*)&As[kk][tm];
            float4 b4 = *(const float4*)&Bs[kk][tn];
            float av[4] = {a4.x, a4.y, a4.z, a4.w};
            float bv[4] = {b4.x, b4.y, b4.z, b4.w};
#pragma unroll
            for (int i = 0; i < 4; i++)
#pragma unroll
                for (int j = 0; j < 4; j++)
                    acc[i][j] = fmaf(av[i], bv[j], acc[i][j]);
        }
        __syncthreads();
    }
#pragma unroll
    for (int i = 0; i < 4; i++) {
        float4 v = make_float4(acc[i][0], acc[i][1], acc[i][2], acc[i][3]);
        *(float4*)(out + (size_t)(m0 + tm + i) * Hn + tn) = v;
    }
}

// ---------------------------------------------------------------------------
// Kernel 2: causal attention with relative-position bias.
// grid (16 q-tiles, 8 batches), 256 threads, dynamic smem.
// Per block: 64 query rows; loop over key tiles of 64 with online softmax.
// Bias handled via per-row table Ds[r][rel] = q_r . E[rel], rel in [0,49].
// Thread mapping: tg=tid>>4 owns rows tr=4*tg..+3; cg=tid&15 owns cols 4*cg..+3
// (both for S's s-columns and O's h-columns). Row stats reduced over 16 lanes.
// ---------------------------------------------------------------------------
__global__ __launch_bounds__(256) void attn_kernel(
    const float* __restrict__ rpe, float* __restrict__ out)
{
    extern __shared__ float sm[];
    float* Qst = sm;                 // [64][68]  Qst[d][r]
    float* Kst = Qst + 64 * 68;      // [64][68]  Kst[d][s]
    float* Vs  = Kst + 64 * 68;      // [64][68]  Vs[s][d]
    float* Prs = Vs  + 64 * 68;      // [64][68]  P[r][s]
    float* Es  = Prs + 64 * 68;      // [50][64]
    float* Ds  = Es  + 50 * 64;      // [64][50]

    const int qt = blockIdx.x, b = blockIdx.y;
    const int tid = threadIdx.x;
    const int tg = tid >> 4, cg = tid & 15;
    const int tr = tg << 2, sc0 = cg << 2;
    const int row0 = b * Tn + qt * 64;

    // load Q tile transposed: Qst[d][r]
#pragma unroll
    for (int it = 0; it < 4; it++) {
        int f = it * 256 + tid;
        int rr = f & 63, dg = f >> 6;
        float4 v = *(const float4*)(g_q + (size_t)(row0 + rr) * Hn + (dg << 2));
        Qst[(dg * 4 + 0) * 68 + rr] = v.x;
        Qst[(dg * 4 + 1) * 68 + rr] = v.y;
        Qst[(dg * 4 + 2) * 68 + rr] = v.z;
        Qst[(dg * 4 + 3) * 68 + rr] = v.w;
    }
    // load rel-pos rows 0..49 (only these reachable under causal mask)
    for (int f = tid; f < 800; f += 256) {
        int rr = f >> 4, dc = (f & 15) << 2;
        *(float4*)&Es[rr * 64 + dc] = *(const float4*)(rpe + (size_t)rr * Hn + dc);
    }
    __syncthreads();
    // bias table Ds[r][rel] = q_r . E[rel]
    for (int idx = tid; idx < 64 * NREL; idx += 256) {
        int rr = idx / NREL, rel = idx - rr * NREL;
        float s = 0.f;
#pragma unroll
        for (int d = 0; d < 64; d++)
            s = fmaf(Qst[d * 68 + rr], Es[rel * 64 + d], s);
        Ds[rr * NREL + rel] = s;
    }

    float mrow[4], lrow[4], acc[4][4];
#pragma unroll
    for (int i = 0; i < 4; i++) {
        mrow[i] = -INFINITY; lrow[i] = 0.f;
#pragma unroll
        for (int j = 0; j < 4; j++) acc[i][j] = 0.f;
    }

    for (int kt = 0; kt <= qt; kt++) {
        __syncthreads();   // prior tile's smem reads done (also covers Ds init)
        const int krow0 = b * Tn + kt * 64;
        // K transposed + V natural
#pragma unroll
        for (int it = 0; it < 4; it++) {
            int f = it * 256 + tid;
            int ss = f & 63, dg = f >> 6;
            float4 v = *(const float4*)(g_k + (size_t)(krow0 + ss) * Hn + (dg << 2));
            Kst[(dg * 4 + 0) * 68 + ss] = v.x;
            Kst[(dg * 4 + 1) * 68 + ss] = v.y;
            Kst[(dg * 4 + 2) * 68 + ss] = v.z;
            Kst[(dg * 4 + 3) * 68 + ss] = v.w;
            int s2 = f >> 4, dc = (f & 15) << 2;
            *(float4*)&Vs[s2 * 68 + dc] =
                *(const float4*)(g_v + (size_t)(krow0 + s2) * Hn + dc);
        }
        __syncthreads();

        // S = Q K^T (4x4 per thread)
        float sv[4][4];
#pragma unroll
        for (int i = 0; i < 4; i++)
#pragma unroll
            for (int j = 0; j < 4; j++) sv[i][j] = 0.f;
#pragma unroll
        for (int d = 0; d < 64; d++) {
            float4 qa = *(const float4*)&Qst[d * 68 + tr];
            float4 kb = *(const float4*)&Kst[d * 68 + sc0];
            float av[4] = {qa.x, qa.y, qa.z, qa.w};
            float bv[4] = {kb.x, kb.y, kb.z, kb.w};
#pragma unroll
            for (int i = 0; i < 4; i++)
#pragma unroll
                for (int j = 0; j < 4; j++)
                    sv[i][j] = fmaf(av[i], bv[j], sv[i][j]);
        }

        // scale + rel-pos bias + causal mask
#pragma unroll
        for (int i = 0; i < 4; i++) {
            const int t_g = qt * 64 + tr + i;
#pragma unroll
            for (int j = 0; j < 4; j++) {
                const int s_g = kt * 64 + sc0 + j;
                int rel = 49 + s_g - t_g;
                rel = rel < 0 ? 0 : (rel > 49 ? 49 : rel);
                float bias = Ds[(tr + i) * NREL + rel];
                sv[i][j] = (s_g > t_g) ? -INFINITY
                                       : fmaf(sv[i][j], QK_SCALE, bias);
            }
        }

        // online softmax (row stats shared by 16 lanes of the half-warp)
#pragma unroll
        for (int i = 0; i < 4; i++) {
            float rm = fmaxf(fmaxf(sv[i][0], sv[i][1]), fmaxf(sv[i][2], sv[i][3]));
#pragma unroll
            for (int o = 1; o < 16; o <<= 1)
                rm = fmaxf(rm, __shfl_xor_sync(0xffffffffu, rm, o));
            float mnew = fmaxf(mrow[i], rm);
            float corr = __expf(mrow[i] - mnew);
            float p0 = __expf(sv[i][0] - mnew);
            float p1 = __expf(sv[i][1] - mnew);
            float p2 = __expf(sv[i][2] - mnew);
            float p3 = __expf(sv[i][3] - mnew);
            *(float4*)&Prs[(tr + i) * 68 + sc0] = make_float4(p0, p1, p2, p3);
            float ps = p0 + p1 + p2 + p3;
#pragma unroll
            for (int o = 1; o < 16; o <<= 1)
                ps += __shfl_xor_sync(0xffffffffu, ps, o);
            lrow[i] = lrow[i] * corr + ps;
            mrow[i] = mnew;
#pragma unroll
            for (int j = 0; j < 4; j++) acc[i][j] *= corr;
        }
        __syncwarp();   // P rows owned by this half-warp only

        // O += P V (4x4 per thread)
#pragma unroll
        for (int s4 = 0; s4 < 16; s4++) {
            float pr[4][4];
#pragma unroll
            for (int i = 0; i < 4; i++) {
                float4 t = *(const float4*)&Prs[(tr + i) * 68 + (s4 << 2)];
                pr[i][0] = t.x; pr[i][1] = t.y; pr[i][2] = t.z; pr[i][3] = t.w;
            }
#pragma unroll
            for (int q = 0; q < 4; q++) {
                float4 vb = *(const float4*)&Vs[(s4 * 4 + q) * 68 + sc0];
                float bv[4] = {vb.x, vb.y, vb.z, vb.w};
#pragma unroll
                for (int i = 0; i < 4; i++)
#pragma unroll
                    for (int j = 0; j < 4; j++)
                        acc[i][j] = fmaf(pr[i][q], bv[j], acc[i][j]);
            }
        }
    }

    // epilogue
#pragma unroll
    for (int i = 0; i < 4; i++) {
        float inv = 1.f / lrow[i];
        float4 o = make_float4(acc[i][0] * inv, acc[i][1] * inv,
                               acc[i][2] * inv, acc[i][3] * inv);
        *(float4*)(out + (size_t)(row0 + tr + i) * Hn + sc0) = o;
    }
}

extern "C" void kernel_launch(void* const* d_in, const int* in_sizes, int n_in,
                              void* d_out, int out_size)
{
    const float* x   = (const float*)d_in[0];
    const float* Wq  = (const float*)d_in[1];
    const float* Wk  = (const float*)d_in[2];
    const float* Wv  = (const float*)d_in[3];
    const float* rpe = (const float*)d_in[4];
    float* out = (float*)d_out;

    const int smem_bytes = (4 * 64 * 68 + 50 * 64 + 64 * 50) * (int)sizeof(float); // 95232
    cudaFuncSetAttribute(attn_kernel,
                         cudaFuncAttributeMaxDynamicSharedMemorySize, smem_bytes);

    qkv_kernel<<<dim3(128, 3), 256>>>(x, Wq, Wk, Wv);
    attn_kernel<<<dim3(16, 8), 256, smem_bytes>>>(rpe, out);
}

// round 2
// speedup vs baseline: 1.0055x; 1.0055x over previous
#include <cuda_runtime.h>
#include <math.h>

#define Bn 8
#define Tn 1024
#define Cn 512
#define Hn 64
#define NREL 50
#define QK_SCALE 0.125f   // 64^-0.5
#define NQT 16            // 1024/64 q-tiles per batch
#define NCH 4             // max kv-chunks per q-tile (256 keys per chunk)
#define NWORK 40          // sum over qt of ceil((qt+1)/4)

// scratch for q,k,v projections: [B*T, H] each
__device__ float g_q[Bn * Tn * Hn];
__device__ float g_k[Bn * Tn * Hn];
__device__ float g_v[Bn * Tn * Hn];

// split-KV partials: slot = (b*16+qt)*4 + ch
__device__ float g_pacc[Bn * NQT * NCH][64 * 64];
__device__ float g_pm[Bn * NQT * NCH][64];
__device__ float g_pl[Bn * NQT * NCH][64];

// work-item -> (qt, chunk) map
__constant__ unsigned char c_qt[NWORK] = {
    0,1,2,3, 4,4, 5,5, 6,6, 7,7,
    8,8,8, 9,9,9, 10,10,10, 11,11,11,
    12,12,12,12, 13,13,13,13, 14,14,14,14, 15,15,15,15};
__constant__ unsigned char c_ch[NWORK] = {
    0,0,0,0, 0,1, 0,1, 0,1, 0,1,
    0,1,2, 0,1,2, 0,1,2, 0,1,2,
    0,1,2,3, 0,1,2,3, 0,1,2,3, 0,1,2,3};

// ---------------------------------------------------------------------------
// Kernel 1: QKV projection. grid (64, 3), 256 threads.
// Tile: BM=128, BN=64 (full H), BK=32. 8x4 register micro-tile.
// ---------------------------------------------------------------------------
__global__ __launch_bounds__(256) void qkv_kernel(
    const float* __restrict__ x, const float* __restrict__ Wq,
    const float* __restrict__ Wk, const float* __restrict__ Wv)
{
    __shared__ float As[32][132];   // As[k][m] (transposed)
    __shared__ float Bs[32][68];    // Bs[k][n]
    const int m0 = blockIdx.x * 128;
    const float* W = blockIdx.y == 0 ? Wq : (blockIdx.y == 1 ? Wk : Wv);
    float* out = blockIdx.y == 0 ? g_q : (blockIdx.y == 1 ? g_k : g_v);
    const int tid = threadIdx.x;
    const int tm = (tid >> 4) << 3;   // 0..120 (8 rows)
    const int tn = (tid & 15) << 2;   // 0..60  (4 cols)

    float acc[8][4];
#pragma unroll
    for (int i = 0; i < 8; i++)
#pragma unroll
        for (int j = 0; j < 4; j++) acc[i][j] = 0.f;

    for (int k0 = 0; k0 < Cn; k0 += 32) {
        // A tile 128x32: coalesced float4 load, transposed scalar store
#pragma unroll
        for (int it = 0; it < 4; it++) {
            int f = it * 256 + tid;
            int r = f >> 3, c = (f & 7) << 2;
            float4 v = *(const float4*)(x + (size_t)(m0 + r) * Cn + k0 + c);
            As[c + 0][r] = v.x; As[c + 1][r] = v.y;
            As[c + 2][r] = v.z; As[c + 3][r] = v.w;
        }
        // B tile 32x64: direct float4 copy
#pragma unroll
        for (int it = 0; it < 2; it++) {
            int f = it * 256 + tid;
            int kr = f >> 4, nc = (f & 15) << 2;
            *(float4*)&Bs[kr][nc] = *(const float4*)(W + (size_t)(k0 + kr) * Hn + nc);
        }
        __syncthreads();
#pragma unroll
        for (int kk = 0; kk < 32; kk++) {
            float4 a0 = *(const float4*)&As[kk][tm];
            float4 a1 = *(const float4*)&As[kk][tm + 4];
            float4 b4 = *(const float4*)&Bs[kk][tn];
            float av[8] = {a0.x, a0.y, a0.z, a0.w, a1.x, a1.y, a1.z, a1.w};
            float bv[4] = {b4.x, b4.y, b4.z, b4.w};
#pragma unroll
            for (int i = 0; i < 8; i++)
#pragma unroll
                for (int j = 0; j < 4; j++)
                    acc[i][j] = fmaf(av[i], bv[j], acc[i][j]);
        }
        __syncthreads();
    }
#pragma unroll
    for (int i = 0; i < 8; i++) {
        float4 v = make_float4(acc[i][0], acc[i][1], acc[i][2], acc[i][3]);
        *(float4*)(out + (size_t)(m0 + tm + i) * Hn + tn) = v;
    }
}

// ---------------------------------------------------------------------------
// Kernel 2: split-KV causal attention partials. grid (40, 8), 256 threads.
// Block = (b, qt, chunk). Chunk = up to 4 key-tiles of 64.
// Writes raw (m, l, acc) partials for later combine.
// Rel-pos bias: only chunks with kt1 >= qt-1 can see rel>0; far chunks use
// the row-constant bias Ds[r][0] (rel clamps to 0 naturally).
// ---------------------------------------------------------------------------
__global__ __launch_bounds__(256) void attn_part_kernel(
    const float* __restrict__ rpe)
{
    extern __shared__ float sm[];
    float* Qst = sm;                 // [64][68]  Qst[d][r]
    float* Kst = Qst + 64 * 68;      // [64][68]  Kst[d][s]
    float* Vs  = Kst + 64 * 68;      // [64][68]  Vs[s][d]
    float* Prs = Vs  + 64 * 68;      // [64][68]  P[r][s]
    float* Es  = Prs + 64 * 68;      // [50][64]
    float* Ds  = Es  + 50 * 64;      // [64][50]

    const int w = blockIdx.x, b = blockIdx.y;
    const int qt = c_qt[w], ch = c_ch[w];
    const int kt0 = ch * 4;
    const int kt1 = min(qt, kt0 + 3);
    const bool near = (kt1 >= qt - 1);

    const int tid = threadIdx.x;
    const int tg = tid >> 4, cg = tid & 15;
    const int tr = tg << 2, sc0 = cg << 2;
    const int row0 = b * Tn + qt * 64;

    // load Q tile transposed: Qst[d][r]
#pragma unroll
    for (int it = 0; it < 4; it++) {
        int f = it * 256 + tid;
        int rr = f & 63, dg = f >> 6;
        float4 v = *(const float4*)(g_q + (size_t)(row0 + rr) * Hn + (dg << 2));
        Qst[(dg * 4 + 0) * 68 + rr] = v.x;
        Qst[(dg * 4 + 1) * 68 + rr] = v.y;
        Qst[(dg * 4 + 2) * 68 + rr] = v.z;
        Qst[(dg * 4 + 3) * 68 + rr] = v.w;
    }

    if (near) {
        // load rel-pos rows 0..49
        for (int f = tid; f < 800; f += 256) {
            int rr = f >> 4, dc = (f & 15) << 2;
            *(float4*)&Es[rr * 64 + dc] = *(const float4*)(rpe + (size_t)rr * Hn + dc);
        }
        __syncthreads();
        // full bias table Ds[r][rel] = q_r . E[rel]
        for (int idx = tid; idx < 64 * NREL; idx += 256) {
            int rr = idx / NREL, rel = idx - rr * NREL;
            float s = 0.f;
#pragma unroll
            for (int d = 0; d < 64; d++)
                s = fmaf(Qst[d * 68 + rr], Es[rel * 64 + d], s);
            Ds[rr * NREL + rel] = s;
        }
    } else {
        // only rel==0 reachable: bias is Ds[r][0] = q_r . E[0]
        if (tid < 16)
            *(float4*)&Es[tid << 2] = *(const float4*)(rpe + (tid << 2));
        __syncthreads();
        if (tid < 64) {
            float s = 0.f;
#pragma unroll
            for (int d = 0; d < 64; d++)
                s = fmaf(Qst[d * 68 + tid], Es[d], s);
            Ds[tid * NREL] = s;
        }
    }

    float mrow[4], lrow[4], acc[4][4];
#pragma unroll
    for (int i = 0; i < 4; i++) {
        mrow[i] = -INFINITY; lrow[i] = 0.f;
#pragma unroll
        for (int j = 0; j < 4; j++) acc[i][j] = 0.f;
    }

    for (int kt = kt0; kt <= kt1; kt++) {
        __syncthreads();   // prior smem reads done (also covers Ds init)
        const int krow0 = b * Tn + kt * 64;
#pragma unroll
        for (int it = 0; it < 4; it++) {
            int f = it * 256 + tid;
            int ss = f & 63, dg = f >> 6;
            float4 v = *(const float4*)(g_k + (size_t)(krow0 + ss) * Hn + (dg << 2));
            Kst[(dg * 4 + 0) * 68 + ss] = v.x;
            Kst[(dg * 4 + 1) * 68 + ss] = v.y;
            Kst[(dg * 4 + 2) * 68 + ss] = v.z;
            Kst[(dg * 4 + 3) * 68 + ss] = v.w;
            int s2 = f >> 4, dc = (f & 15) << 2;
            *(float4*)&Vs[s2 * 68 + dc] =
                *(const float4*)(g_v + (size_t)(krow0 + s2) * Hn + dc);
        }
        __syncthreads();

        // S = Q K^T (4x4 per thread)
        float sv[4][4];
#pragma unroll
        for (int i = 0; i < 4; i++)
#pragma unroll
            for (int j = 0; j < 4; j++) sv[i][j] = 0.f;
#pragma unroll
        for (int d = 0; d < 64; d++) {
            float4 qa = *(const float4*)&Qst[d * 68 + tr];
            float4 kb = *(const float4*)&Kst[d * 68 + sc0];
            float av[4] = {qa.x, qa.y, qa.z, qa.w};
            float bv[4] = {kb.x, kb.y, kb.z, kb.w};
#pragma unroll
            for (int i = 0; i < 4; i++)
#pragma unroll
                for (int j = 0; j < 4; j++)
                    sv[i][j] = fmaf(av[i], bv[j], sv[i][j]);
        }

        // scale + rel-pos bias + causal mask
#pragma unroll
        for (int i = 0; i < 4; i++) {
            const int t_g = qt * 64 + tr + i;
#pragma unroll
            for (int j = 0; j < 4; j++) {
                const int s_g = kt * 64 + sc0 + j;
                int rel = 49 + s_g - t_g;
                rel = rel < 0 ? 0 : (rel > 49 ? 49 : rel);
                float bias = Ds[(tr + i) * NREL + rel];
                sv[i][j] = (s_g > t_g) ? -INFINITY
                                       : fmaf(sv[i][j], QK_SCALE, bias);
            }
        }

        // online softmax
#pragma unroll
        for (int i = 0; i < 4; i++) {
            float rm = fmaxf(fmaxf(sv[i][0], sv[i][1]), fmaxf(sv[i][2], sv[i][3]));
#pragma unroll
            for (int o = 1; o < 16; o <<= 1)
                rm = fmaxf(rm, __shfl_xor_sync(0xffffffffu, rm, o));
            float mnew = fmaxf(mrow[i], rm);
            float corr = __expf(mrow[i] - mnew);
            float p0 = __expf(sv[i][0] - mnew);
            float p1 = __expf(sv[i][1] - mnew);
            float p2 = __expf(sv[i][2] - mnew);
            float p3 = __expf(sv[i][3] - mnew);
            *(float4*)&Prs[(tr + i) * 68 + sc0] = make_float4(p0, p1, p2, p3);
            float ps = p0 + p1 + p2 + p3;
#pragma unroll
            for (int o = 1; o < 16; o <<= 1)
                ps += __shfl_xor_sync(0xffffffffu, ps, o);
            lrow[i] = lrow[i] * corr + ps;
            mrow[i] = mnew;
#pragma unroll
            for (int j = 0; j < 4; j++) acc[i][j] *= corr;
        }
        __syncwarp();

        // O += P V
#pragma unroll
        for (int s4 = 0; s4 < 16; s4++) {
            float pr[4][4];
#pragma unroll
            for (int i = 0; i < 4; i++) {
                float4 t = *(const float4*)&Prs[(tr + i) * 68 + (s4 << 2)];
                pr[i][0] = t.x; pr[i][1] = t.y; pr[i][2] = t.z; pr[i][3] = t.w;
            }
#pragma unroll
            for (int q = 0; q < 4; q++) {
                float4 vb = *(const float4*)&Vs[(s4 * 4 + q) * 68 + sc0];
                float bv[4] = {vb.x, vb.y, vb.z, vb.w};
#pragma unroll
                for (int i = 0; i < 4; i++)
#pragma unroll
                    for (int j = 0; j < 4; j++)
                        acc[i][j] = fmaf(pr[i][q], bv[j], acc[i][j]);
            }
        }
    }

    // epilogue: write raw partial to scratch
    const int slot = (b * NQT + qt) * NCH + ch;
    float* pa = g_pacc[slot];
#pragma unroll
    for (int i = 0; i < 4; i++) {
        float4 o = make_float4(acc[i][0], acc[i][1], acc[i][2], acc[i][3]);
        *(float4*)(pa + (tr + i) * 64 + sc0) = o;
    }
    if (cg == 0) {
#pragma unroll
        for (int i = 0; i < 4; i++) {
            g_pm[slot][tr + i] = mrow[i];
            g_pl[slot][tr + i] = lrow[i];
        }
    }
}

// ---------------------------------------------------------------------------
// Kernel 3: combine partials. grid (16, 8), 256 threads.
// Thread handles one row r, 16 of 64 h-columns.
// ---------------------------------------------------------------------------
__global__ __launch_bounds__(256) void combine_kernel(float* __restrict__ out)
{
    const int qt = blockIdx.x, b = blockIdx.y;
    const int n = (qt >> 2) + 1;            // chunks for this qt
    const int base = (b * NQT + qt) * NCH;
    const int tid = threadIdx.x;
    const int r = tid >> 2;
    const int hc = (tid & 3) << 4;

    float m[NCH], wgt[NCH];
    float M = -INFINITY;
    for (int c = 0; c < n; c++) {
        m[c] = g_pm[base + c][r];
        M = fmaxf(M, m[c]);
    }
    float L = 0.f;
    for (int c = 0; c < n; c++) {
        wgt[c] = __expf(m[c] - M);
        L += g_pl[base + c][r] * wgt[c];
    }
    float invL = 1.f / L;

    float4 o[4];
#pragma unroll
    for (int j = 0; j < 4; j++) o[j] = make_float4(0.f, 0.f, 0.f, 0.f);
    for (int c = 0; c < n; c++) {
        const float wc = wgt[c] * invL;
        const float* pa = g_pacc[base + c] + r * 64 + hc;
#pragma unroll
        for (int j = 0; j < 4; j++) {
            float4 v = *(const float4*)(pa + 4 * j);
            o[j].x = fmaf(wc, v.x, o[j].x);
            o[j].y = fmaf(wc, v.y, o[j].y);
            o[j].z = fmaf(wc, v.z, o[j].z);
            o[j].w = fmaf(wc, v.w, o[j].w);
        }
    }
    float* op = out + (size_t)(b * Tn + qt * 64 + r) * Hn + hc;
#pragma unroll
    for (int j = 0; j < 4; j++)
        *(float4*)(op + 4 * j) = o[j];
}

extern "C" void kernel_launch(void* const* d_in, const int* in_sizes, int n_in,
                              void* d_out, int out_size)
{
    const float* x   = (const float*)d_in[0];
    const float* Wq  = (const float*)d_in[1];
    const float* Wk  = (const float*)d_in[2];
    const float* Wv  = (const float*)d_in[3];
    const float* rpe = (const float*)d_in[4];
    float* out = (float*)d_out;

    const int smem_bytes = (4 * 64 * 68 + 50 * 64 + 64 * 50) * (int)sizeof(float); // 95232
    cudaFuncSetAttribute(attn_part_kernel,
                         cudaFuncAttributeMaxDynamicSharedMemorySize, smem_bytes);

    qkv_kernel<<<dim3(64, 3), 256>>>(x, Wq, Wk, Wv);
    attn_part_kernel<<<dim3(NWORK, 8), 256, smem_bytes>>>(rpe);
    combine_kernel<<<dim3(NQT, 8), 256>>>(out);
}

// round 3
// speedup vs baseline: 1.4242x; 1.4164x over previous
#include <cuda_runtime.h>
#include <math.h>

#define Bn 8
#define Tn 1024
#define Cn 512
#define Hn 64
#define NREL 50
#define QK_SCALE 0.125f   // 64^-0.5
#define NQT 16            // 1024/64 q-tiles per batch
#define NCH 4             // max kv-chunks per q-tile (256 keys per chunk)
#define NWORK 40          // sum over qt of ceil((qt+1)/4)

// scratch for q,k,v projections: [B*T, H] each
__device__ float g_q[Bn * Tn * Hn];
__device__ float g_k[Bn * Tn * Hn];
__device__ float g_v[Bn * Tn * Hn];

// split-KV partials: slot = (b*16+qt)*4 + ch
__device__ float g_pacc[Bn * NQT * NCH][64 * 64];
__device__ float g_pm[Bn * NQT * NCH][64];
__device__ float g_pl[Bn * NQT * NCH][64];

// work-item -> (qt, chunk) map
__constant__ unsigned char c_qt[NWORK] = {
    0,1,2,3, 4,4, 5,5, 6,6, 7,7,
    8,8,8, 9,9,9, 10,10,10, 11,11,11,
    12,12,12,12, 13,13,13,13, 14,14,14,14, 15,15,15,15};
__constant__ unsigned char c_ch[NWORK] = {
    0,0,0,0, 0,1, 0,1, 0,1, 0,1,
    0,1,2, 0,1,2, 0,1,2, 0,1,2,
    0,1,2,3, 0,1,2,3, 0,1,2,3, 0,1,2,3};

// ---------------------------------------------------------------------------
// Kernel 1: QKV projection. grid (128, 3), 256 threads.
// Tile: BM=64, BN=64 (full H), BK=64. 4x4 register micro-tile.
// 384 blocks -> 2.6 blocks/SM; BK=64 halves barrier count vs BK=32.
// ---------------------------------------------------------------------------
__global__ __launch_bounds__(256) void qkv_kernel(
    const float* __restrict__ x, const float* __restrict__ Wq,
    const float* __restrict__ Wk, const float* __restrict__ Wv)
{
    __shared__ float As[64][68];   // As[k][m] (transposed)
    __shared__ float Bs[64][68];   // Bs[k][n]
    const int m0 = blockIdx.x * 64;
    const float* W = blockIdx.y == 0 ? Wq : (blockIdx.y == 1 ? Wk : Wv);
    float* out = blockIdx.y == 0 ? g_q : (blockIdx.y == 1 ? g_k : g_v);
    const int tid = threadIdx.x;
    const int tm = (tid >> 4) << 2;   // 0..60
    const int tn = (tid & 15) << 2;   // 0..60

    float acc[4][4];
#pragma unroll
    for (int i = 0; i < 4; i++)
#pragma unroll
        for (int j = 0; j < 4; j++) acc[i][j] = 0.f;

    for (int k0 = 0; k0 < Cn; k0 += 64) {
        // A tile 64x64: coalesced float4 load, transposed scalar store
#pragma unroll
        for (int it = 0; it < 4; it++) {
            int f = it * 256 + tid;
            int r = f >> 4, c = (f & 15) << 2;
            float4 v = *(const float4*)(x + (size_t)(m0 + r) * Cn + k0 + c);
            As[c + 0][r] = v.x; As[c + 1][r] = v.y;
            As[c + 2][r] = v.z; As[c + 3][r] = v.w;
        }
        // B tile 64x64: direct float4 copy
#pragma unroll
        for (int it = 0; it < 4; it++) {
            int f = it * 256 + tid;
            int kr = f >> 4, nc = (f & 15) << 2;
            *(float4*)&Bs[kr][nc] = *(const float4*)(W + (size_t)(k0 + kr) * Hn + nc);
        }
        __syncthreads();
#pragma unroll
        for (int kk = 0; kk < 64; kk++) {
            float4 a4 = *(const float4*)&As[kk][tm];
            float4 b4 = *(const float4*)&Bs[kk][tn];
            float av[4] = {a4.x, a4.y, a4.z, a4.w};
            float bv[4] = {b4.x, b4.y, b4.z, b4.w};
#pragma unroll
            for (int i = 0; i < 4; i++)
#pragma unroll
                for (int j = 0; j < 4; j++)
                    acc[i][j] = fmaf(av[i], bv[j], acc[i][j]);
        }
        __syncthreads();
    }
#pragma unroll
    for (int i = 0; i < 4; i++) {
        float4 v = make_float4(acc[i][0], acc[i][1], acc[i][2], acc[i][3]);
        *(float4*)(out + (size_t)(m0 + tm + i) * Hn + tn) = v;
    }
}

// ---------------------------------------------------------------------------
// Kernel 2: split-KV causal attention partials. grid (40, 8), 256 threads.
// Block = (b, qt, chunk). Chunk = up to 4 key-tiles of 64.
// Bias: near-diagonal chunks compute Ds = Q E^T as a conflict-free 64x64 GEMM
// (E transposed into the K smem region); far chunks only need rel==0.
// ---------------------------------------------------------------------------
__global__ __launch_bounds__(256) void attn_part_kernel(
    const float* __restrict__ rpe)
{
    extern __shared__ float sm[];
    float* Qst = sm;                 // [64][68]  Qst[d][r]
    float* Kst = Qst + 64 * 68;      // [64][68]  Kst[d][s]   (also Est[d][rel])
    float* Vs  = Kst + 64 * 68;      // [64][68]  Vs[s][d]
    float* Prs = Vs  + 64 * 68;      // [64][68]  P[r][s]
    float* Ds  = Prs + 64 * 68;      // [64][68]  bias[r][rel] (cols >=50 unused)

    const int w = blockIdx.x, b = blockIdx.y;
    const int qt = c_qt[w], ch = c_ch[w];
    const int kt0 = ch * 4;
    const int kt1 = min(qt, kt0 + 3);
    const bool near = (kt1 >= qt - 1);

    const int tid = threadIdx.x;
    const int tg = tid >> 4, cg = tid & 15;
    const int tr = tg << 2, sc0 = cg << 2;
    const int row0 = b * Tn + qt * 64;

    // load Q tile transposed: Qst[d][r]
#pragma unroll
    for (int it = 0; it < 4; it++) {
        int f = it * 256 + tid;
        int rr = f & 63, dg = f >> 6;
        float4 v = *(const float4*)(g_q + (size_t)(row0 + rr) * Hn + (dg << 2));
        Qst[(dg * 4 + 0) * 68 + rr] = v.x;
        Qst[(dg * 4 + 1) * 68 + rr] = v.y;
        Qst[(dg * 4 + 2) * 68 + rr] = v.z;
        Qst[(dg * 4 + 3) * 68 + rr] = v.w;
    }

    if (near) {
        // load E transposed into Kst: Kst[d][rel], rel in [0,50)
        for (int f = tid; f < 800; f += 256) {
            int rr = f >> 4, dg = f & 15;     // rr = rel row, dg = d-group
            float4 v = *(const float4*)(rpe + (size_t)rr * Hn + (dg << 2));
            Kst[(dg * 4 + 0) * 68 + rr] = v.x;
            Kst[(dg * 4 + 1) * 68 + rr] = v.y;
            Kst[(dg * 4 + 2) * 68 + rr] = v.z;
            Kst[(dg * 4 + 3) * 68 + rr] = v.w;
        }
        __syncthreads();
        // Ds = Q E^T via the same 4x4 micro-kernel (cols >= 50 are garbage,
        // never read). Conflict-free float4 LDS.
        float sv[4][4];
#pragma unroll
        for (int i = 0; i < 4; i++)
#pragma unroll
            for (int j = 0; j < 4; j++) sv[i][j] = 0.f;
#pragma unroll
        for (int d = 0; d < 64; d++) {
            float4 qa = *(const float4*)&Qst[d * 68 + tr];
            float4 eb = *(const float4*)&Kst[d * 68 + sc0];
            float av[4] = {qa.x, qa.y, qa.z, qa.w};
            float bv[4] = {eb.x, eb.y, eb.z, eb.w};
#pragma unroll
            for (int i = 0; i < 4; i++)
#pragma unroll
                for (int j = 0; j < 4; j++)
                    sv[i][j] = fmaf(av[i], bv[j], sv[i][j]);
        }
#pragma unroll
        for (int i = 0; i < 4; i++)
            *(float4*)&Ds[(tr + i) * 68 + sc0] =
                make_float4(sv[i][0], sv[i][1], sv[i][2], sv[i][3]);
    } else {
        // only rel==0 reachable: bias is Ds[r][0] = q_r . E[0]
        if (tid < 16)
            *(float4*)&Kst[tid << 2] = *(const float4*)(rpe + (tid << 2));
        __syncthreads();
        if (tid < 64) {
            float s = 0.f;
#pragma unroll
            for (int d = 0; d < 64; d++)
                s = fmaf(Qst[d * 68 + tid], Kst[d], s);
            Ds[tid * 68] = s;
        }
    }

    float mrow[4], lrow[4], acc[4][4];
#pragma unroll
    for (int i = 0; i < 4; i++) {
        mrow[i] = -INFINITY; lrow[i] = 0.f;
#pragma unroll
        for (int j = 0; j < 4; j++) acc[i][j] = 0.f;
    }

    for (int kt = kt0; kt <= kt1; kt++) {
        __syncthreads();   // prior smem reads done (covers Ds/Est phase too)
        const int krow0 = b * Tn + kt * 64;
#pragma unroll
        for (int it = 0; it < 4; it++) {
            int f = it * 256 + tid;
            int ss = f & 63, dg = f >> 6;
            float4 v = *(const float4*)(g_k + (size_t)(krow0 + ss) * Hn + (dg << 2));
            Kst[(dg * 4 + 0) * 68 + ss] = v.x;
            Kst[(dg * 4 + 1) * 68 + ss] = v.y;
            Kst[(dg * 4 + 2) * 68 + ss] = v.z;
            Kst[(dg * 4 + 3) * 68 + ss] = v.w;
            int s2 = f >> 4, dc = (f & 15) << 2;
            *(float4*)&Vs[s2 * 68 + dc] =
                *(const float4*)(g_v + (size_t)(krow0 + s2) * Hn + dc);
        }
        __syncthreads();

        // S = Q K^T (4x4 per thread)
        float sv[4][4];
#pragma unroll
        for (int i = 0; i < 4; i++)
#pragma unroll
            for (int j = 0; j < 4; j++) sv[i][j] = 0.f;
#pragma unroll
        for (int d = 0; d < 64; d++) {
            float4 qa = *(const float4*)&Qst[d * 68 + tr];
            float4 kb = *(const float4*)&Kst[d * 68 + sc0];
            float av[4] = {qa.x, qa.y, qa.z, qa.w};
            float bv[4] = {kb.x, kb.y, kb.z, kb.w};
#pragma unroll
            for (int i = 0; i < 4; i++)
#pragma unroll
                for (int j = 0; j < 4; j++)
                    sv[i][j] = fmaf(av[i], bv[j], sv[i][j]);
        }

        // scale + rel-pos bias + causal mask
#pragma unroll
        for (int i = 0; i < 4; i++) {
            const int t_g = qt * 64 + tr + i;
#pragma unroll
            for (int j = 0; j < 4; j++) {
                const int s_g = kt * 64 + sc0 + j;
                int rel = 49 + s_g - t_g;
                rel = rel < 0 ? 0 : (rel > 49 ? 49 : rel);
                float bias = Ds[(tr + i) * 68 + rel];
                sv[i][j] = (s_g > t_g) ? -INFINITY
                                       : fmaf(sv[i][j], QK_SCALE, bias);
            }
        }

        // online softmax (row stats shared by 16 lanes)
#pragma unroll
        for (int i = 0; i < 4; i++) {
            float rm = fmaxf(fmaxf(sv[i][0], sv[i][1]), fmaxf(sv[i][2], sv[i][3]));
#pragma unroll
            for (int o = 1; o < 16; o <<= 1)
                rm = fmaxf(rm, __shfl_xor_sync(0xffffffffu, rm, o));
            float mnew = fmaxf(mrow[i], rm);
            float corr = __expf(mrow[i] - mnew);
            float p0 = __expf(sv[i][0] - mnew);
            float p1 = __expf(sv[i][1] - mnew);
            float p2 = __expf(sv[i][2] - mnew);
            float p3 = __expf(sv[i][3] - mnew);
            *(float4*)&Prs[(tr + i) * 68 + sc0] = make_float4(p0, p1, p2, p3);
            float ps = p0 + p1 + p2 + p3;
#pragma unroll
            for (int o = 1; o < 16; o <<= 1)
                ps += __shfl_xor_sync(0xffffffffu, ps, o);
            lrow[i] = lrow[i] * corr + ps;
            mrow[i] = mnew;
#pragma unroll
            for (int j = 0; j < 4; j++) acc[i][j] *= corr;
        }
        __syncwarp();

        // O += P V
#pragma unroll
        for (int s4 = 0; s4 < 16; s4++) {
            float pr[4][4];
#pragma unroll
            for (int i = 0; i < 4; i++) {
                float4 t = *(const float4*)&Prs[(tr + i) * 68 + (s4 << 2)];
                pr[i][0] = t.x; pr[i][1] = t.y; pr[i][2] = t.z; pr[i][3] = t.w;
            }
#pragma unroll
            for (int q = 0; q < 4; q++) {
                float4 vb = *(const float4*)&Vs[(s4 * 4 + q) * 68 + sc0];
                float bv[4] = {vb.x, vb.y, vb.z, vb.w};
#pragma unroll
                for (int i = 0; i < 4; i++)
#pragma unroll
                    for (int j = 0; j < 4; j++)
                        acc[i][j] = fmaf(pr[i][q], bv[j], acc[i][j]);
            }
        }
    }

    // epilogue: write raw partial to scratch
    const int slot = (b * NQT + qt) * NCH + ch;
    float* pa = g_pacc[slot];
#pragma unroll
    for (int i = 0; i < 4; i++) {
        float4 o = make_float4(acc[i][0], acc[i][1], acc[i][2], acc[i][3]);
        *(float4*)(pa + (tr + i) * 64 + sc0) = o;
    }
    if (cg == 0) {
#pragma unroll
        for (int i = 0; i < 4; i++) {
            g_pm[slot][tr + i] = mrow[i];
            g_pl[slot][tr + i] = lrow[i];
        }
    }
}

// ---------------------------------------------------------------------------
// Kernel 3: combine partials. grid (16, 8), 256 threads.
// ---------------------------------------------------------------------------
__global__ __launch_bounds__(256) void combine_kernel(float* __restrict__ out)
{
    const int qt = blockIdx.x, b = blockIdx.y;
    const int n = (qt >> 2) + 1;            // chunks for this qt
    const int base = (b * NQT + qt) * NCH;
    const int tid = threadIdx.x;
    const int r = tid >> 2;
    const int hc = (tid & 3) << 4;

    float m[NCH], wgt[NCH];
    float M = -INFINITY;
    for (int c = 0; c < n; c++) {
        m[c] = g_pm[base + c][r];
        M = fmaxf(M, m[c]);
    }
    float L = 0.f;
    for (int c = 0; c < n; c++) {
        wgt[c] = __expf(m[c] - M);
        L += g_pl[base + c][r] * wgt[c];
    }
    float invL = 1.f / L;

    float4 o[4];
#pragma unroll
    for (int j = 0; j < 4; j++) o[j] = make_float4(0.f, 0.f, 0.f, 0.f);
    for (int c = 0; c < n; c++) {
        const float wc = wgt[c] * invL;
        const float* pa = g_pacc[base + c] + r * 64 + hc;
#pragma unroll
        for (int j = 0; j < 4; j++) {
            float4 v = *(const float4*)(pa + 4 * j);
            o[j].x = fmaf(wc, v.x, o[j].x);
            o[j].y = fmaf(wc, v.y, o[j].y);
            o[j].z = fmaf(wc, v.z, o[j].z);
            o[j].w = fmaf(wc, v.w, o[j].w);
        }
    }
    float* op = out + (size_t)(b * Tn + qt * 64 + r) * Hn + hc;
#pragma unroll
    for (int j = 0; j < 4; j++)
        *(float4*)(op + 4 * j) = o[j];
}

extern "C" void kernel_launch(void* const* d_in, const int* in_sizes, int n_in,
                              void* d_out, int out_size)
{
    const float* x   = (const float*)d_in[0];
    const float* Wq  = (const float*)d_in[1];
    const float* Wk  = (const float*)d_in[2];
    const float* Wv  = (const float*)d_in[3];
    const float* rpe = (const float*)d_in[4];
    float* out = (float*)d_out;

    const int smem_bytes = 5 * 64 * 68 * (int)sizeof(float); // 87040
    cudaFuncSetAttribute(attn_part_kernel,
                         cudaFuncAttributeMaxDynamicSharedMemorySize, smem_bytes);

    qkv_kernel<<<dim3(128, 3), 256>>>(x, Wq, Wk, Wv);
    attn_part_kernel<<<dim3(NWORK, 8), 256, smem_bytes>>>(rpe);
    combine_kernel<<<dim3(NQT, 8), 256>>>(out);
}

// round 5
// speedup vs baseline: 2.0353x; 1.4291x over previous
#include <cuda_runtime.h>
#include <cuda_bf16.h>
#include <math.h>
#include <stdint.h>

#define Bn 8
#define Tn 1024
#define Cn 512
#define Hn 64
#define NREL 50
#define QK_SCALE 0.125f   // 64^-0.5
#define NQT 16
#define NCH 4
#define NWORK 40

// fp32 q,k,v for the attention kernels
__device__ float g_q[Bn * Tn * Hn];
__device__ float g_k[Bn * Tn * Hn];
__device__ float g_v[Bn * Tn * Hn];

// split-bf16 W^T: rows [0,64)=Wq^T [64,128)=Wk^T [128,192)=Wv^T, row stride Cn
__device__ __nv_bfloat16 g_wth[192 * Cn];
__device__ __nv_bfloat16 g_wtl[192 * Cn];

// split-KV partials
__device__ float g_pacc[Bn * NQT * NCH][64 * 64];
__device__ float g_pm[Bn * NQT * NCH][64];
__device__ float g_pl[Bn * NQT * NCH][64];

__constant__ unsigned char c_qt[NWORK] = {
    0,1,2,3, 4,4, 5,5, 6,6, 7,7,
    8,8,8, 9,9,9, 10,10,10, 11,11,11,
    12,12,12,12, 13,13,13,13, 14,14,14,14, 15,15,15,15};
__constant__ unsigned char c_ch[NWORK] = {
    0,0,0,0, 0,1, 0,1, 0,1, 0,1,
    0,1,2, 0,1,2, 0,1,2, 0,1,2,
    0,1,2,3, 0,1,2,3, 0,1,2,3, 0,1,2,3};

// ---------------------------------------------------------------------------
// helpers
// ---------------------------------------------------------------------------
__device__ __forceinline__ uint32_t smem_u32(const void* p) {
    uint32_t a;
    asm("{ .reg .u64 t; cvta.to.shared.u64 t, %1; cvt.u32.u64 %0, t; }"
        : "=r"(a) : "l"(p));
    return a;
}
#define LDM_X4(r0, r1, r2, r3, a) \
    asm volatile("ldmatrix.sync.aligned.m8n8.x4.shared.b16 {%0,%1,%2,%3}, [%4];" \
                 : "=r"(r0), "=r"(r1), "=r"(r2), "=r"(r3) : "r"(a))
#define LDM_X2(r0, r1, a) \
    asm volatile("ldmatrix.sync.aligned.m8n8.x2.shared.b16 {%0,%1}, [%2];" \
                 : "=r"(r0), "=r"(r1) : "r"(a))
#define MMA_BF16(d, a, b) \
    asm volatile("mma.sync.aligned.m16n8k16.row.col.f32.bf16.bf16.f32 " \
                 "{%0,%1,%2,%3}, {%4,%5,%6,%7}, {%8,%9}, {%0,%1,%2,%3};" \
                 : "+f"((d)[0]), "+f"((d)[1]), "+f"((d)[2]), "+f"((d)[3]) \
                 : "r"((a)[0]), "r"((a)[1]), "r"((a)[2]), "r"((a)[3]), \
                   "r"((b)[0]), "r"((b)[1]))

__device__ __forceinline__ uint32_t pack_bf16(float x, float y) {
    __nv_bfloat162 h(__float2bfloat16(x), __float2bfloat16(y));
    return *(uint32_t*)&h;
}

// ---------------------------------------------------------------------------
// Convert + transpose weights: g_wt*[n][k] from W[k][n%64]. grid 384 x 256.
// ---------------------------------------------------------------------------
__global__ __launch_bounds__(256) void cvt_w_kernel(
    const float* __restrict__ Wq, const float* __restrict__ Wk,
    const float* __restrict__ Wv)
{
    int idx = blockIdx.x * 256 + threadIdx.x;       // [0, 192*512)
    int n = idx >> 9, k = idx & 511;
    const float* W = (n < 64) ? Wq : (n < 128 ? Wk : Wv);
    float v = W[(size_t)k * Hn + (n & 63)];
    __nv_bfloat16 h = __float2bfloat16(v);
    g_wth[idx] = h;
    g_wtl[idx] = __float2bfloat16(v - __bfloat162float(h));
}

// ---------------------------------------------------------------------------
// QKV projection on mma.sync bf16 (split hi/lo). grid 128, 256 threads.
// Per CTA: M=64 rows, N=192 (q|k|v), K in 8 chunks of 64.
// Warp grid 2x4: warp tile 32 rows x 48 cols = 2 m-tiles x 6 n-tiles.
// Smem rows padded to 72 halves (144B) -> conflict-free ldmatrix.
// ---------------------------------------------------------------------------
#define PAD 72
#define SM_AH 0
#define SM_AL 9216
#define SM_BH 18432
#define SM_BL 46080
#define QKV_SMEM 73728

__global__ __launch_bounds__(256, 1) void qkv_mma_kernel(const float* __restrict__ x)
{
    extern __shared__ char smem[];
    const uint32_t sb = smem_u32(smem);
    const int tid = threadIdx.x;
    const int wid = tid >> 5, lane = tid & 31;
    const int wm = wid >> 2, wn = wid & 3;
    const int m0 = blockIdx.x * 64;

    float acc[2][6][4];
#pragma unroll
    for (int mt = 0; mt < 2; mt++)
#pragma unroll
        for (int nt = 0; nt < 6; nt++)
#pragma unroll
            for (int e = 0; e < 4; e++) acc[mt][nt][e] = 0.f;

    // precomputed ldmatrix lane addressing
    const int aq = lane >> 3, ai = lane & 7;            // x4: quadrant, row
    const int arow_off = (aq & 1) * 8 + ai;             // within 16-row tile
    const int akoff = (aq >> 1) * 8;
    const int bi = lane & 7, bh8 = ((lane >> 3) & 1) * 8;   // x2 (lanes>=16 dup)

    for (int c = 0; c < 8; c++) {
        if (c) __syncthreads();
        const int kc = c * 64;
        // A: 64 rows x 64 k fp32 -> hi/lo bf16 smem
#pragma unroll
        for (int it = 0; it < 4; it++) {
            int f = it * 256 + tid;
            int r = f >> 4, kq = (f & 15) << 2;
            float4 v = *(const float4*)(x + (size_t)(m0 + r) * Cn + kc + kq);
            uint32_t h0 = pack_bf16(v.x, v.y), h1 = pack_bf16(v.z, v.w);
            float lx = v.x - __bfloat162float(__ushort_as_bfloat16((unsigned short)(h0 & 0xffff)));
            float ly = v.y - __bfloat162float(__ushort_as_bfloat16((unsigned short)(h0 >> 16)));
            float lz = v.z - __bfloat162float(__ushort_as_bfloat16((unsigned short)(h1 & 0xffff)));
            float lw = v.w - __bfloat162float(__ushort_as_bfloat16((unsigned short)(h1 >> 16)));
            uint32_t l0 = pack_bf16(lx, ly), l1 = pack_bf16(lz, lw);
            uint32_t off = (uint32_t)(r * PAD + kq) * 2;
            *(uint2*)(smem + SM_AH + off) = make_uint2(h0, h1);
            *(uint2*)(smem + SM_AL + off) = make_uint2(l0, l1);
        }
        // B: 192 rows x 64 k bf16 copy
#pragma unroll
        for (int it = 0; it < 6; it++) {
            int f = it * 256 + tid;
            int n = f >> 3, kq = (f & 7) << 3;
            uint32_t off = (uint32_t)(n * PAD + kq) * 2;
            *(uint4*)(smem + SM_BH + off) =
                *(const uint4*)(g_wth + (size_t)n * Cn + kc + kq);
            *(uint4*)(smem + SM_BL + off) =
                *(const uint4*)(g_wtl + (size_t)n * Cn + kc + kq);
        }
        __syncthreads();

#pragma unroll
        for (int ks = 0; ks < 4; ks++) {
            const int K = ks * 16;
            uint32_t ah[2][4], al[2][4];
#pragma unroll
            for (int mt = 0; mt < 2; mt++) {
                uint32_t ao = (uint32_t)((wm * 32 + mt * 16 + arow_off) * PAD
                                         + K + akoff) * 2;
                LDM_X4(ah[mt][0], ah[mt][1], ah[mt][2], ah[mt][3], sb + SM_AH + ao);
                LDM_X4(al[mt][0], al[mt][1], al[mt][2], al[mt][3], sb + SM_AL + ao);
            }
#pragma unroll
            for (int nt = 0; nt < 6; nt++) {
                uint32_t bo = (uint32_t)((wn * 48 + nt * 8 + bi) * PAD
                                         + K + bh8) * 2;
                uint32_t bh[2], bl[2];
                LDM_X2(bh[0], bh[1], sb + SM_BH + bo);
                LDM_X2(bl[0], bl[1], sb + SM_BL + bo);
#pragma unroll
                for (int mt = 0; mt < 2; mt++) {
                    MMA_BF16(acc[mt][nt], ah[mt], bh);
                    MMA_BF16(acc[mt][nt], ah[mt], bl);
                    MMA_BF16(acc[mt][nt], al[mt], bh);
                }
            }
        }
    }

    // epilogue: D fragment -> g_q/g_k/g_v
    const int g = lane >> 2, t = lane & 3;
#pragma unroll
    for (int mt = 0; mt < 2; mt++) {
#pragma unroll
        for (int nt = 0; nt < 6; nt++) {
            const int c0 = wn * 48 + nt * 8 + 2 * t;
            float* dst = (c0 < 64) ? g_q : (c0 < 128 ? g_k : g_v);
            const int cc = c0 & 63;
            const size_t row = (size_t)m0 + wm * 32 + mt * 16 + g;
            *(float2*)(dst + row * Hn + cc) =
                make_float2(acc[mt][nt][0], acc[mt][nt][1]);
            *(float2*)(dst + (row + 8) * Hn + cc) =
                make_float2(acc[mt][nt][2], acc[mt][nt][3]);
        }
    }
}

// ---------------------------------------------------------------------------
// Kernel: split-KV causal attention partials. grid (40, 8), 256 threads.
// ---------------------------------------------------------------------------
__global__ __launch_bounds__(256) void attn_part_kernel(
    const float* __restrict__ rpe)
{
    extern __shared__ float sm[];
    float* Qst = sm;                 // [64][68]
    float* Kst = Qst + 64 * 68;      // [64][68] (also E^T)
    float* Vs  = Kst + 64 * 68;      // [64][68]
    float* Prs = Vs  + 64 * 68;      // [64][68]
    float* Ds  = Prs + 64 * 68;      // [64][68] bias (cols>=50 unused)

    const int w = blockIdx.x, b = blockIdx.y;
    const int qt = c_qt[w], ch = c_ch[w];
    const int kt0 = ch * 4;
    const int kt1 = min(qt, kt0 + 3);
    const bool near = (kt1 >= qt - 1);

    const int tid = threadIdx.x;
    const int tg = tid >> 4, cg = tid & 15;
    const int tr = tg << 2, sc0 = cg << 2;
    const int row0 = b * Tn + qt * 64;

#pragma unroll
    for (int it = 0; it < 4; it++) {
        int f = it * 256 + tid;
        int rr = f & 63, dg = f >> 6;
        float4 v = *(const float4*)(g_q + (size_t)(row0 + rr) * Hn + (dg << 2));
        Qst[(dg * 4 + 0) * 68 + rr] = v.x;
        Qst[(dg * 4 + 1) * 68 + rr] = v.y;
        Qst[(dg * 4 + 2) * 68 + rr] = v.z;
        Qst[(dg * 4 + 3) * 68 + rr] = v.w;
    }

    if (near) {
        for (int f = tid; f < 800; f += 256) {
            int rr = f >> 4, dg = f & 15;
            float4 v = *(const float4*)(rpe + (size_t)rr * Hn + (dg << 2));
            Kst[(dg * 4 + 0) * 68 + rr] = v.x;
            Kst[(dg * 4 + 1) * 68 + rr] = v.y;
            Kst[(dg * 4 + 2) * 68 + rr] = v.z;
            Kst[(dg * 4 + 3) * 68 + rr] = v.w;
        }
        __syncthreads();
        float sv[4][4];
#pragma unroll
        for (int i = 0; i < 4; i++)
#pragma unroll
            for (int j = 0; j < 4; j++) sv[i][j] = 0.f;
#pragma unroll
        for (int d = 0; d < 64; d++) {
            float4 qa = *(const float4*)&Qst[d * 68 + tr];
            float4 eb = *(const float4*)&Kst[d * 68 + sc0];
            float av[4] = {qa.x, qa.y, qa.z, qa.w};
            float bv[4] = {eb.x, eb.y, eb.z, eb.w};
#pragma unroll
            for (int i = 0; i < 4; i++)
#pragma unroll
                for (int j = 0; j < 4; j++)
                    sv[i][j] = fmaf(av[i], bv[j], sv[i][j]);
        }
#pragma unroll
        for (int i = 0; i < 4; i++)
            *(float4*)&Ds[(tr + i) * 68 + sc0] =
                make_float4(sv[i][0], sv[i][1], sv[i][2], sv[i][3]);
    } else {
        if (tid < 16)
            *(float4*)&Kst[tid << 2] = *(const float4*)(rpe + (tid << 2));
        __syncthreads();
        if (tid < 64) {
            float s = 0.f;
#pragma unroll
            for (int d = 0; d < 64; d++)
                s = fmaf(Qst[d * 68 + tid], Kst[d], s);
            Ds[tid * 68] = s;
        }
    }

    float mrow[4], lrow[4], acc[4][4];
#pragma unroll
    for (int i = 0; i < 4; i++) {
        mrow[i] = -INFINITY; lrow[i] = 0.f;
#pragma unroll
        for (int j = 0; j < 4; j++) acc[i][j] = 0.f;
    }

    for (int kt = kt0; kt <= kt1; kt++) {
        __syncthreads();
        const int krow0 = b * Tn + kt * 64;
#pragma unroll
        for (int it = 0; it < 4; it++) {
            int f = it * 256 + tid;
            int ss = f & 63, dg = f >> 6;
            float4 v = *(const float4*)(g_k + (size_t)(krow0 + ss) * Hn + (dg << 2));
            Kst[(dg * 4 + 0) * 68 + ss] = v.x;
            Kst[(dg * 4 + 1) * 68 + ss] = v.y;
            Kst[(dg * 4 + 2) * 68 + ss] = v.z;
            Kst[(dg * 4 + 3) * 68 + ss] = v.w;
            int s2 = f >> 4, dc = (f & 15) << 2;
            *(float4*)&Vs[s2 * 68 + dc] =
                *(const float4*)(g_v + (size_t)(krow0 + s2) * Hn + dc);
        }
        __syncthreads();

        float sv[4][4];
#pragma unroll
        for (int i = 0; i < 4; i++)
#pragma unroll
            for (int j = 0; j < 4; j++) sv[i][j] = 0.f;
#pragma unroll
        for (int d = 0; d < 64; d++) {
            float4 qa = *(const float4*)&Qst[d * 68 + tr];
            float4 kb = *(const float4*)&Kst[d * 68 + sc0];
            float av[4] = {qa.x, qa.y, qa.z, qa.w};
            float bv[4] = {kb.x, kb.y, kb.z, kb.w};
#pragma unroll
            for (int i = 0; i < 4; i++)
#pragma unroll
                for (int j = 0; j < 4; j++)
                    sv[i][j] = fmaf(av[i], bv[j], sv[i][j]);
        }

#pragma unroll
        for (int i = 0; i < 4; i++) {
            const int t_g = qt * 64 + tr + i;
#pragma unroll
            for (int j = 0; j < 4; j++) {
                const int s_g = kt * 64 + sc0 + j;
                int rel = 49 + s_g - t_g;
                rel = rel < 0 ? 0 : (rel > 49 ? 49 : rel);
                float bias = Ds[(tr + i) * 68 + rel];
                sv[i][j] = (s_g > t_g) ? -INFINITY
                                       : fmaf(sv[i][j], QK_SCALE, bias);
            }
        }

#pragma unroll
        for (int i = 0; i < 4; i++) {
            float rm = fmaxf(fmaxf(sv[i][0], sv[i][1]), fmaxf(sv[i][2], sv[i][3]));
#pragma unroll
            for (int o = 1; o < 16; o <<= 1)
                rm = fmaxf(rm, __shfl_xor_sync(0xffffffffu, rm, o));
            float mnew = fmaxf(mrow[i], rm);
            float corr = __expf(mrow[i] - mnew);
            float p0 = __expf(sv[i][0] - mnew);
            float p1 = __expf(sv[i][1] - mnew);
            float p2 = __expf(sv[i][2] - mnew);
            float p3 = __expf(sv[i][3] - mnew);
            *(float4*)&Prs[(tr + i) * 68 + sc0] = make_float4(p0, p1, p2, p3);
            float ps = p0 + p1 + p2 + p3;
#pragma unroll
            for (int o = 1; o < 16; o <<= 1)
                ps += __shfl_xor_sync(0xffffffffu, ps, o);
            lrow[i] = lrow[i] * corr + ps;
            mrow[i] = mnew;
#pragma unroll
            for (int j = 0; j < 4; j++) acc[i][j] *= corr;
        }
        __syncwarp();

#pragma unroll
        for (int s4 = 0; s4 < 16; s4++) {
            float pr[4][4];
#pragma unroll
            for (int i = 0; i < 4; i++) {
                float4 t = *(const float4*)&Prs[(tr + i) * 68 + (s4 << 2)];
                pr[i][0] = t.x; pr[i][1] = t.y; pr[i][2] = t.z; pr[i][3] = t.w;
            }
#pragma unroll
            for (int q = 0; q < 4; q++) {
                float4 vb = *(const float4*)&Vs[(s4 * 4 + q) * 68 + sc0];
                float bv[4] = {vb.x, vb.y, vb.z, vb.w};
#pragma unroll
                for (int i = 0; i < 4; i++)
#pragma unroll
                    for (int j = 0; j < 4; j++)
                        acc[i][j] = fmaf(pr[i][q], bv[j], acc[i][j]);
            }
        }
    }

    const int slot = (b * NQT + qt) * NCH + ch;
    float* pa = g_pacc[slot];
#pragma unroll
    for (int i = 0; i < 4; i++) {
        float4 o = make_float4(acc[i][0], acc[i][1], acc[i][2], acc[i][3]);
        *(float4*)(pa + (tr + i) * 64 + sc0) = o;
    }
    if (cg == 0) {
#pragma unroll
        for (int i = 0; i < 4; i++) {
            g_pm[slot][tr + i] = mrow[i];
            g_pl[slot][tr + i] = lrow[i];
        }
    }
}

// ---------------------------------------------------------------------------
// Kernel: combine partials. grid (16, 8), 256 threads.
// ---------------------------------------------------------------------------
__global__ __launch_bounds__(256) void combine_kernel(float* __restrict__ out)
{
    const int qt = blockIdx.x, b = blockIdx.y;
    const int n = (qt >> 2) + 1;
    const int base = (b * NQT + qt) * NCH;
    const int tid = threadIdx.x;
    const int r = tid >> 2;
    const int hc = (tid & 3) << 4;

    float m[NCH], wgt[NCH];
    float M = -INFINITY;
    for (int c = 0; c < n; c++) {
        m[c] = g_pm[base + c][r];
        M = fmaxf(M, m[c]);
    }
    float L = 0.f;
    for (int c = 0; c < n; c++) {
        wgt[c] = __expf(m[c] - M);
        L += g_pl[base + c][r] * wgt[c];
    }
    float invL = 1.f / L;

    float4 o[4];
#pragma unroll
    for (int j = 0; j < 4; j++) o[j] = make_float4(0.f, 0.f, 0.f, 0.f);
    for (int c = 0; c < n; c++) {
        const float wc = wgt[c] * invL;
        const float* pa = g_pacc[base + c] + r * 64 + hc;
#pragma unroll
        for (int j = 0; j < 4; j++) {
            float4 v = *(const float4*)(pa + 4 * j);
            o[j].x = fmaf(wc, v.x, o[j].x);
            o[j].y = fmaf(wc, v.y, o[j].y);
            o[j].z = fmaf(wc, v.z, o[j].z);
            o[j].w = fmaf(wc, v.w, o[j].w);
        }
    }
    float* op = out + (size_t)(b * Tn + qt * 64 + r) * Hn + hc;
#pragma unroll
    for (int j = 0; j < 4; j++)
        *(float4*)(op + 4 * j) = o[j];
}

extern "C" void kernel_launch(void* const* d_in, const int* in_sizes, int n_in,
                              void* d_out, int out_size)
{
    const float* x   = (const float*)d_in[0];
    const float* Wq  = (const float*)d_in[1];
    const float* Wk  = (const float*)d_in[2];
    const float* Wv  = (const float*)d_in[3];
    const float* rpe = (const float*)d_in[4];
    float* out = (float*)d_out;

    const int attn_smem = 5 * 64 * 68 * (int)sizeof(float); // 87040
    cudaFuncSetAttribute(attn_part_kernel,
                         cudaFuncAttributeMaxDynamicSharedMemorySize, attn_smem);
    cudaFuncSetAttribute(qkv_mma_kernel,
                         cudaFuncAttributeMaxDynamicSharedMemorySize, QKV_SMEM);

    cvt_w_kernel<<<384, 256>>>(Wq, Wk, Wv);
    qkv_mma_kernel<<<128, 256, QKV_SMEM>>>(x);
    attn_part_kernel<<<dim3(NWORK, 8), 256, attn_smem>>>(rpe);
    combine_kernel<<<dim3(NQT, 8), 256>>>(out);
}

// round 6
// speedup vs baseline: 2.9415x; 1.4452x over previous
#include <cuda_runtime.h>
#include <cuda_bf16.h>
#include <math.h>
#include <stdint.h>

#define Bn 8
#define Tn 1024
#define Cn 512
#define Hn 64
#define NREL 50
#define QK_SCALE 0.125f   // 64^-0.5
#define NQT 16
#define NCH 4
#define NWORK 40

// split-bf16 q,k (row-major [B*T][64]) and v transposed ([B][64][T])
__device__ __nv_bfloat16 g_qh[Bn * Tn * Hn];
__device__ __nv_bfloat16 g_ql[Bn * Tn * Hn];
__device__ __nv_bfloat16 g_kh[Bn * Tn * Hn];
__device__ __nv_bfloat16 g_kl[Bn * Tn * Hn];
__device__ __nv_bfloat16 g_vth[Bn * Hn * Tn];
__device__ __nv_bfloat16 g_vtl[Bn * Hn * Tn];

// split-bf16 W^T: rows [0,64)=Wq^T [64,128)=Wk^T [128,192)=Wv^T
__device__ __nv_bfloat16 g_wth[192 * Cn];
__device__ __nv_bfloat16 g_wtl[192 * Cn];

// split-KV partials
__device__ float g_pacc[Bn * NQT * NCH][64 * 64];
__device__ float g_pm[Bn * NQT * NCH][64];
__device__ float g_pl[Bn * NQT * NCH][64];

__constant__ unsigned char c_qt[NWORK] = {
    0,1,2,3, 4,4, 5,5, 6,6, 7,7,
    8,8,8, 9,9,9, 10,10,10, 11,11,11,
    12,12,12,12, 13,13,13,13, 14,14,14,14, 15,15,15,15};
__constant__ unsigned char c_ch[NWORK] = {
    0,0,0,0, 0,1, 0,1, 0,1, 0,1,
    0,1,2, 0,1,2, 0,1,2, 0,1,2,
    0,1,2,3, 0,1,2,3, 0,1,2,3, 0,1,2,3};

// ---------------------------------------------------------------------------
// helpers
// ---------------------------------------------------------------------------
__device__ __forceinline__ uint32_t smem_u32(const void* p) {
    uint32_t a;
    asm("{ .reg .u64 t; cvta.to.shared.u64 t, %1; cvt.u32.u64 %0, t; }"
        : "=r"(a) : "l"(p));
    return a;
}
#define LDM_X4(r0, r1, r2, r3, a) \
    asm volatile("ldmatrix.sync.aligned.m8n8.x4.shared.b16 {%0,%1,%2,%3}, [%4];" \
                 : "=r"(r0), "=r"(r1), "=r"(r2), "=r"(r3) : "r"(a))
#define LDM_X2(r0, r1, a) \
    asm volatile("ldmatrix.sync.aligned.m8n8.x2.shared.b16 {%0,%1}, [%2];" \
                 : "=r"(r0), "=r"(r1) : "r"(a))
#define MMA_BF16(d, a, b) \
    asm volatile("mma.sync.aligned.m16n8k16.row.col.f32.bf16.bf16.f32 " \
                 "{%0,%1,%2,%3}, {%4,%5,%6,%7}, {%8,%9}, {%0,%1,%2,%3};" \
                 : "+f"((d)[0]), "+f"((d)[1]), "+f"((d)[2]), "+f"((d)[3]) \
                 : "r"((a)[0]), "r"((a)[1]), "r"((a)[2]), "r"((a)[3]), \
                   "r"((b)[0]), "r"((b)[1]))

__device__ __forceinline__ void split2(float f0, float f1,
                                       uint32_t& h, uint32_t& l) {
    __nv_bfloat16 h0 = __float2bfloat16(f0), h1 = __float2bfloat16(f1);
    __nv_bfloat16 l0 = __float2bfloat16(f0 - __bfloat162float(h0));
    __nv_bfloat16 l1 = __float2bfloat16(f1 - __bfloat162float(h1));
    __nv_bfloat162 hh(h0, h1), ll(l0, l1);
    h = *(uint32_t*)&hh; l = *(uint32_t*)&ll;
}
__device__ __forceinline__ uint32_t pack_bf16(float x, float y) {
    __nv_bfloat162 h(__float2bfloat16(x), __float2bfloat16(y));
    return *(uint32_t*)&h;
}

// ---------------------------------------------------------------------------
// Convert + transpose weights. grid 384 x 256.
// ---------------------------------------------------------------------------
__global__ __launch_bounds__(256) void cvt_w_kernel(
    const float* __restrict__ Wq, const float* __restrict__ Wk,
    const float* __restrict__ Wv)
{
    int idx = blockIdx.x * 256 + threadIdx.x;
    int n = idx >> 9, k = idx & 511;
    const float* W = (n < 64) ? Wq : (n < 128 ? Wk : Wv);
    float v = W[(size_t)k * Hn + (n & 63)];
    __nv_bfloat16 h = __float2bfloat16(v);
    g_wth[idx] = h;
    g_wtl[idx] = __float2bfloat16(v - __bfloat162float(h));
}

// ---------------------------------------------------------------------------
// QKV projection on mma.sync bf16 (split hi/lo). grid 128, 256 threads.
// Epilogue emits split-bf16 q,k (row-major) and v transposed.
// ---------------------------------------------------------------------------
#define PAD 72
#define SM_AH 0
#define SM_AL 9216
#define SM_BH 18432
#define SM_BL 46080
#define QKV_SMEM 73728

__global__ __launch_bounds__(256, 1) void qkv_mma_kernel(const float* __restrict__ x)
{
    extern __shared__ char smem[];
    const uint32_t sb = smem_u32(smem);
    const int tid = threadIdx.x;
    const int wid = tid >> 5, lane = tid & 31;
    const int wm = wid >> 2, wn = wid & 3;
    const int m0 = blockIdx.x * 64;

    float acc[2][6][4];
#pragma unroll
    for (int mt = 0; mt < 2; mt++)
#pragma unroll
        for (int nt = 0; nt < 6; nt++)
#pragma unroll
            for (int e = 0; e < 4; e++) acc[mt][nt][e] = 0.f;

    const int aq = lane >> 3, ai = lane & 7;
    const int arow_off = (aq & 1) * 8 + ai;
    const int akoff = (aq >> 1) * 8;
    const int bi = lane & 7, bh8 = ((lane >> 3) & 1) * 8;

    for (int c = 0; c < 8; c++) {
        if (c) __syncthreads();
        const int kc = c * 64;
#pragma unroll
        for (int it = 0; it < 4; it++) {
            int f = it * 256 + tid;
            int r = f >> 4, kq = (f & 15) << 2;
            float4 v = *(const float4*)(x + (size_t)(m0 + r) * Cn + kc + kq);
            uint32_t h0, l0, h1, l1;
            split2(v.x, v.y, h0, l0);
            split2(v.z, v.w, h1, l1);
            uint32_t off = (uint32_t)(r * PAD + kq) * 2;
            *(uint2*)(smem + SM_AH + off) = make_uint2(h0, h1);
            *(uint2*)(smem + SM_AL + off) = make_uint2(l0, l1);
        }
#pragma unroll
        for (int it = 0; it < 6; it++) {
            int f = it * 256 + tid;
            int n = f >> 3, kq = (f & 7) << 3;
            uint32_t off = (uint32_t)(n * PAD + kq) * 2;
            *(uint4*)(smem + SM_BH + off) =
                *(const uint4*)(g_wth + (size_t)n * Cn + kc + kq);
            *(uint4*)(smem + SM_BL + off) =
                *(const uint4*)(g_wtl + (size_t)n * Cn + kc + kq);
        }
        __syncthreads();

#pragma unroll
        for (int ks = 0; ks < 4; ks++) {
            const int K = ks * 16;
            uint32_t ah[2][4], al[2][4];
#pragma unroll
            for (int mt = 0; mt < 2; mt++) {
                uint32_t ao = (uint32_t)((wm * 32 + mt * 16 + arow_off) * PAD
                                         + K + akoff) * 2;
                LDM_X4(ah[mt][0], ah[mt][1], ah[mt][2], ah[mt][3], sb + SM_AH + ao);
                LDM_X4(al[mt][0], al[mt][1], al[mt][2], al[mt][3], sb + SM_AL + ao);
            }
#pragma unroll
            for (int nt = 0; nt < 6; nt++) {
                uint32_t bo = (uint32_t)((wn * 48 + nt * 8 + bi) * PAD
                                         + K + bh8) * 2;
                uint32_t bh[2], bl[2];
                LDM_X2(bh[0], bh[1], sb + SM_BH + bo);
                LDM_X2(bl[0], bl[1], sb + SM_BL + bo);
#pragma unroll
                for (int mt = 0; mt < 2; mt++) {
                    MMA_BF16(acc[mt][nt], ah[mt], bh);
                    MMA_BF16(acc[mt][nt], ah[mt], bl);
                    MMA_BF16(acc[mt][nt], al[mt], bh);
                }
            }
        }
    }

    // epilogue
    const int g = lane >> 2, t = lane & 3;
#pragma unroll
    for (int mt = 0; mt < 2; mt++) {
#pragma unroll
        for (int nt = 0; nt < 6; nt++) {
            const int c0 = wn * 48 + nt * 8 + 2 * t;
            const size_t row = (size_t)m0 + wm * 32 + mt * 16 + g;
            if (c0 < 128) {
                __nv_bfloat16* dh = (c0 < 64) ? g_qh : g_kh;
                __nv_bfloat16* dl = (c0 < 64) ? g_ql : g_kl;
                const int cc = c0 & 63;
                uint32_t h, l;
                split2(acc[mt][nt][0], acc[mt][nt][1], h, l);
                *(uint32_t*)(dh + row * Hn + cc) = h;
                *(uint32_t*)(dl + row * Hn + cc) = l;
                split2(acc[mt][nt][2], acc[mt][nt][3], h, l);
                *(uint32_t*)(dh + (row + 8) * Hn + cc) = h;
                *(uint32_t*)(dl + (row + 8) * Hn + cc) = l;
            } else {
                const int cc = c0 - 128;
                const size_t bb = row >> 10;
#pragma unroll
                for (int rr = 0; rr < 2; rr++) {
                    const size_t s = (row + rr * 8) & 1023;
                    float f0 = acc[mt][nt][rr * 2], f1 = acc[mt][nt][rr * 2 + 1];
                    __nv_bfloat16 h0 = __float2bfloat16(f0);
                    __nv_bfloat16 h1 = __float2bfloat16(f1);
                    g_vth[bb * 65536 + (size_t)cc * 1024 + s] = h0;
                    g_vtl[bb * 65536 + (size_t)cc * 1024 + s] =
                        __float2bfloat16(f0 - __bfloat162float(h0));
                    g_vth[bb * 65536 + (size_t)(cc + 1) * 1024 + s] = h1;
                    g_vtl[bb * 65536 + (size_t)(cc + 1) * 1024 + s] =
                        __float2bfloat16(f1 - __bfloat162float(h1));
                }
            }
        }
    }
}

// ---------------------------------------------------------------------------
// Tensor-core split-KV attention partials. grid (40, 8), 256 threads.
// ---------------------------------------------------------------------------
#define PADH 72
#define SM_QH  0
#define SM_QL  9216
#define SM_KH  18432
#define SM_KL  27648
#define SM_VTH 36864
#define SM_VTL 46080
#define SM_PH  55296
#define SM_PL  64512
#define SM_SS  73728      // fp32 [64][68]
#define SM_DS  91136      // fp32 [64][68]
#define SM_CORR 108544    // fp32 [64]
#define ATTN_SMEM 108800

__global__ __launch_bounds__(256) void attn_part_kernel(
    const float* __restrict__ rpe)
{
    extern __shared__ char smem[];
    const uint32_t sb = smem_u32(smem);
    float* Ss = (float*)(smem + SM_SS);
    float* Ds = (float*)(smem + SM_DS);
    float* Cs = (float*)(smem + SM_CORR);

    const int w = blockIdx.x, b = blockIdx.y;
    const int qt = c_qt[w], ch = c_ch[w];
    const int kt0 = ch * 4;
    const int kt1 = min(qt, kt0 + 3);

    const int tid = threadIdx.x;
    const int wid = tid >> 5, lane = tid & 31;
    const int wm = wid >> 2, wn = wid & 3;
    const int g = lane >> 2, t = lane & 3;
    const int aq = lane >> 3, ai = lane & 7;
    const int arow_off = (aq & 1) * 8 + ai;
    const int akoff = (aq >> 1) * 8;
    const int bi = lane & 7, bh8 = ((lane >> 3) & 1) * 8;

    const int tg = tid >> 4, cg = tid & 15;
    const int tr = tg << 2, sc0 = cg << 2;
    const int row0 = b * Tn + qt * 64;

    // ---- load Q (hi/lo) ----
#pragma unroll
    for (int it = 0; it < 2; it++) {
        int f = it * 256 + tid;
        int r = f >> 3, cq = f & 7;
        uint32_t off = (uint32_t)(r * PADH + cq * 8) * 2;
        *(uint4*)(smem + SM_QH + off) =
            *(const uint4*)(g_qh + (size_t)(row0 + r) * Hn + cq * 8);
        *(uint4*)(smem + SM_QL + off) =
            *(const uint4*)(g_ql + (size_t)(row0 + r) * Hn + cq * 8);
    }
    // ---- load E (hi/lo) into K buffers; rows >= 50 zero ----
#pragma unroll
    for (int it = 0; it < 4; it++) {
        int f = it * 256 + tid;
        int r = f >> 4, cq = (f & 15) << 2;
        float4 v = make_float4(0.f, 0.f, 0.f, 0.f);
        if (r < NREL) v = *(const float4*)(rpe + (size_t)r * Hn + cq);
        uint32_t h0, l0, h1, l1;
        split2(v.x, v.y, h0, l0);
        split2(v.z, v.w, h1, l1);
        uint32_t off = (uint32_t)(r * PADH + cq) * 2;
        *(uint2*)(smem + SM_KH + off) = make_uint2(h0, h1);
        *(uint2*)(smem + SM_KL + off) = make_uint2(l0, l1);
    }
    __syncthreads();

    // ---- bias GEMM: Ds = Q E^T (3-split mma) ----
    {
        float dacc[2][2][4];
#pragma unroll
        for (int mt = 0; mt < 2; mt++)
#pragma unroll
            for (int nt = 0; nt < 2; nt++)
#pragma unroll
                for (int e = 0; e < 4; e++) dacc[mt][nt][e] = 0.f;
#pragma unroll
        for (int ks = 0; ks < 4; ks++) {
            const int K = ks * 16;
            uint32_t ah[2][4], al[2][4];
#pragma unroll
            for (int mt = 0; mt < 2; mt++) {
                uint32_t ao = (uint32_t)((wm * 32 + mt * 16 + arow_off) * PADH
                                         + K + akoff) * 2;
                LDM_X4(ah[mt][0], ah[mt][1], ah[mt][2], ah[mt][3], sb + SM_QH + ao);
                LDM_X4(al[mt][0], al[mt][1], al[mt][2], al[mt][3], sb + SM_QL + ao);
            }
#pragma unroll
            for (int nt = 0; nt < 2; nt++) {
                uint32_t bo = (uint32_t)((wn * 16 + nt * 8 + bi) * PADH
                                         + K + bh8) * 2;
                uint32_t bh[2], bl[2];
                LDM_X2(bh[0], bh[1], sb + SM_KH + bo);
                LDM_X2(bl[0], bl[1], sb + SM_KL + bo);
#pragma unroll
                for (int mt = 0; mt < 2; mt++) {
                    MMA_BF16(dacc[mt][nt], ah[mt], bh);
                    MMA_BF16(dacc[mt][nt], ah[mt], bl);
                    MMA_BF16(dacc[mt][nt], al[mt], bh);
                }
            }
        }
#pragma unroll
        for (int mt = 0; mt < 2; mt++)
#pragma unroll
            for (int nt = 0; nt < 2; nt++) {
                int row = wm * 32 + mt * 16 + g, col = wn * 16 + nt * 8 + 2 * t;
                *(float2*)&Ds[row * 68 + col] =
                    make_float2(dacc[mt][nt][0], dacc[mt][nt][1]);
                *(float2*)&Ds[(row + 8) * 68 + col] =
                    make_float2(dacc[mt][nt][2], dacc[mt][nt][3]);
            }
    }

    float mrow[4], lrow[4];
#pragma unroll
    for (int i = 0; i < 4; i++) { mrow[i] = -INFINITY; lrow[i] = 0.f; }
    float acc_o[2][2][4];
#pragma unroll
    for (int mt = 0; mt < 2; mt++)
#pragma unroll
        for (int nt = 0; nt < 2; nt++)
#pragma unroll
            for (int e = 0; e < 4; e++) acc_o[mt][nt][e] = 0.f;

    for (int kt = kt0; kt <= kt1; kt++) {
        __syncthreads();   // prior K/V/P readers done (also bias-phase reads)
        const int krow0 = b * Tn + kt * 64;
#pragma unroll
        for (int it = 0; it < 2; it++) {
            int f = it * 256 + tid;
            int r = f >> 3, cq = f & 7;
            uint32_t off = (uint32_t)(r * PADH + cq * 8) * 2;
            *(uint4*)(smem + SM_KH + off) =
                *(const uint4*)(g_kh + (size_t)(krow0 + r) * Hn + cq * 8);
            *(uint4*)(smem + SM_KL + off) =
                *(const uint4*)(g_kl + (size_t)(krow0 + r) * Hn + cq * 8);
            // V^T rows: d = r, s-range of this key tile
            *(uint4*)(smem + SM_VTH + off) =
                *(const uint4*)(g_vth + (size_t)b * 65536 + (size_t)r * 1024
                                + kt * 64 + cq * 8);
            *(uint4*)(smem + SM_VTL + off) =
                *(const uint4*)(g_vtl + (size_t)b * 65536 + (size_t)r * 1024
                                + kt * 64 + cq * 8);
        }
        __syncthreads();

        // ---- S = Q K^T ----
        float sacc[2][2][4];
#pragma unroll
        for (int mt = 0; mt < 2; mt++)
#pragma unroll
            for (int nt = 0; nt < 2; nt++)
#pragma unroll
                for (int e = 0; e < 4; e++) sacc[mt][nt][e] = 0.f;
#pragma unroll
        for (int ks = 0; ks < 4; ks++) {
            const int K = ks * 16;
            uint32_t ah[2][4], al[2][4];
#pragma unroll
            for (int mt = 0; mt < 2; mt++) {
                uint32_t ao = (uint32_t)((wm * 32 + mt * 16 + arow_off) * PADH
                                         + K + akoff) * 2;
                LDM_X4(ah[mt][0], ah[mt][1], ah[mt][2], ah[mt][3], sb + SM_QH + ao);
                LDM_X4(al[mt][0], al[mt][1], al[mt][2], al[mt][3], sb + SM_QL + ao);
            }
#pragma unroll
            for (int nt = 0; nt < 2; nt++) {
                uint32_t bo = (uint32_t)((wn * 16 + nt * 8 + bi) * PADH
                                         + K + bh8) * 2;
                uint32_t bh[2], bl[2];
                LDM_X2(bh[0], bh[1], sb + SM_KH + bo);
                LDM_X2(bl[0], bl[1], sb + SM_KL + bo);
#pragma unroll
                for (int mt = 0; mt < 2; mt++) {
                    MMA_BF16(sacc[mt][nt], ah[mt], bh);
                    MMA_BF16(sacc[mt][nt], ah[mt], bl);
                    MMA_BF16(sacc[mt][nt], al[mt], bh);
                }
            }
        }
#pragma unroll
        for (int mt = 0; mt < 2; mt++)
#pragma unroll
            for (int nt = 0; nt < 2; nt++) {
                int row = wm * 32 + mt * 16 + g, col = wn * 16 + nt * 8 + 2 * t;
                *(float2*)&Ss[row * 68 + col] =
                    make_float2(sacc[mt][nt][0], sacc[mt][nt][1]);
                *(float2*)&Ss[(row + 8) * 68 + col] =
                    make_float2(sacc[mt][nt][2], sacc[mt][nt][3]);
            }
        __syncthreads();

        // ---- softmax (rows tr..tr+3, cols sc0..sc0+3 per thread) ----
#pragma unroll
        for (int i = 0; i < 4; i++) {
            const int t_g = qt * 64 + tr + i;
            float sv[4];
            float4 s4 = *(const float4*)&Ss[(tr + i) * 68 + sc0];
            sv[0] = s4.x; sv[1] = s4.y; sv[2] = s4.z; sv[3] = s4.w;
#pragma unroll
            for (int j = 0; j < 4; j++) {
                const int s_g = kt * 64 + sc0 + j;
                int rel = 49 + s_g - t_g;
                rel = rel < 0 ? 0 : (rel > 49 ? 49 : rel);
                float bias = Ds[(tr + i) * 68 + rel];
                sv[j] = (s_g > t_g) ? -INFINITY : fmaf(sv[j], QK_SCALE, bias);
            }
            float rm = fmaxf(fmaxf(sv[0], sv[1]), fmaxf(sv[2], sv[3]));
#pragma unroll
            for (int o = 1; o < 16; o <<= 1)
                rm = fmaxf(rm, __shfl_xor_sync(0xffffffffu, rm, o));
            float mnew = fmaxf(mrow[i], rm);
            float corr = __expf(mrow[i] - mnew);
            float p0 = __expf(sv[0] - mnew);
            float p1 = __expf(sv[1] - mnew);
            float p2 = __expf(sv[2] - mnew);
            float p3 = __expf(sv[3] - mnew);
            uint32_t h0, l0, h1, l1;
            split2(p0, p1, h0, l0);
            split2(p2, p3, h1, l1);
            uint32_t off = (uint32_t)((tr + i) * PADH + sc0) * 2;
            *(uint2*)(smem + SM_PH + off) = make_uint2(h0, h1);
            *(uint2*)(smem + SM_PL + off) = make_uint2(l0, l1);
            float ps = p0 + p1 + p2 + p3;
#pragma unroll
            for (int o = 1; o < 16; o <<= 1)
                ps += __shfl_xor_sync(0xffffffffu, ps, o);
            lrow[i] = lrow[i] * corr + ps;
            mrow[i] = mnew;
            if (cg == 0) Cs[tr + i] = corr;
        }
        __syncthreads();

        // ---- scale O fragments, then O += P V ----
#pragma unroll
        for (int mt = 0; mt < 2; mt++) {
            float c0r = Cs[wm * 32 + mt * 16 + g];
            float c1r = Cs[wm * 32 + mt * 16 + g + 8];
#pragma unroll
            for (int nt = 0; nt < 2; nt++) {
                acc_o[mt][nt][0] *= c0r; acc_o[mt][nt][1] *= c0r;
                acc_o[mt][nt][2] *= c1r; acc_o[mt][nt][3] *= c1r;
            }
        }
#pragma unroll
        for (int ks = 0; ks < 4; ks++) {
            const int K = ks * 16;
            uint32_t ah[2][4], al[2][4];
#pragma unroll
            for (int mt = 0; mt < 2; mt++) {
                uint32_t ao = (uint32_t)((wm * 32 + mt * 16 + arow_off) * PADH
                                         + K + akoff) * 2;
                LDM_X4(ah[mt][0], ah[mt][1], ah[mt][2], ah[mt][3], sb + SM_PH + ao);
                LDM_X4(al[mt][0], al[mt][1], al[mt][2], al[mt][3], sb + SM_PL + ao);
            }
#pragma unroll
            for (int nt = 0; nt < 2; nt++) {
                uint32_t bo = (uint32_t)((wn * 16 + nt * 8 + bi) * PADH
                                         + K + bh8) * 2;
                uint32_t bh[2], bl[2];
                LDM_X2(bh[0], bh[1], sb + SM_VTH + bo);
                LDM_X2(bl[0], bl[1], sb + SM_VTL + bo);
#pragma unroll
                for (int mt = 0; mt < 2; mt++) {
                    MMA_BF16(acc_o[mt][nt], ah[mt], bh);
                    MMA_BF16(acc_o[mt][nt], ah[mt], bl);
                    MMA_BF16(acc_o[mt][nt], al[mt], bh);
                }
            }
        }
    }

    // ---- epilogue: raw partials ----
    const int slot = (b * NQT + qt) * NCH + ch;
    float* pa = g_pacc[slot];
#pragma unroll
    for (int mt = 0; mt < 2; mt++)
#pragma unroll
        for (int nt = 0; nt < 2; nt++) {
            int row = wm * 32 + mt * 16 + g, col = wn * 16 + nt * 8 + 2 * t;
            *(float2*)(pa + row * 64 + col) =
                make_float2(acc_o[mt][nt][0], acc_o[mt][nt][1]);
            *(float2*)(pa + (row + 8) * 64 + col) =
                make_float2(acc_o[mt][nt][2], acc_o[mt][nt][3]);
        }
    if (cg == 0) {
#pragma unroll
        for (int i = 0; i < 4; i++) {
            g_pm[slot][tr + i] = mrow[i];
            g_pl[slot][tr + i] = lrow[i];
        }
    }
}

// ---------------------------------------------------------------------------
// Combine partials. grid (16, 8), 1024 threads (one float4 per thread).
// ---------------------------------------------------------------------------
__global__ __launch_bounds__(1024) void combine_kernel(float* __restrict__ out)
{
    const int qt = blockIdx.x, b = blockIdx.y;
    const int n = (qt >> 2) + 1;
    const int base = (b * NQT + qt) * NCH;
    const int tid = threadIdx.x;
    const int r = tid >> 4;
    const int hc = (tid & 15) << 2;

    float m[NCH], wgt[NCH];
    float M = -INFINITY;
    for (int c = 0; c < n; c++) {
        m[c] = g_pm[base + c][r];
        M = fmaxf(M, m[c]);
    }
    float L = 0.f;
    for (int c = 0; c < n; c++) {
        wgt[c] = __expf(m[c] - M);
        L += g_pl[base + c][r] * wgt[c];
    }
    float invL = 1.f / L;

    float4 o = make_float4(0.f, 0.f, 0.f, 0.f);
    for (int c = 0; c < n; c++) {
        const float wc = wgt[c] * invL;
        float4 v = *(const float4*)(g_pacc[base + c] + r * 64 + hc);
        o.x = fmaf(wc, v.x, o.x);
        o.y = fmaf(wc, v.y, o.y);
        o.z = fmaf(wc, v.z, o.z);
        o.w = fmaf(wc, v.w, o.w);
    }
    *(float4*)(out + (size_t)(b * Tn + qt * 64 + r) * Hn + hc) = o;
}

extern "C" void kernel_launch(void* const* d_in, const int* in_sizes, int n_in,
                              void* d_out, int out_size)
{
    const float* x   = (const float*)d_in[0];
    const float* Wq  = (const float*)d_in[1];
    const float* Wk  = (const float*)d_in[2];
    const float* Wv  = (const float*)d_in[3];
    const float* rpe = (const float*)d_in[4];
    float* out = (float*)d_out;

    cudaFuncSetAttribute(qkv_mma_kernel,
                         cudaFuncAttributeMaxDynamicSharedMemorySize, QKV_SMEM);
    cudaFuncSetAttribute(attn_part_kernel,
                         cudaFuncAttributeMaxDynamicSharedMemorySize, ATTN_SMEM);

    cvt_w_kernel<<<384, 256>>>(Wq, Wk, Wv);
    qkv_mma_kernel<<<128, 256, QKV_SMEM>>>(x);
    attn_part_kernel<<<dim3(NWORK, 8), 256, ATTN_SMEM>>>(rpe);
    combine_kernel<<<dim3(NQT, 8), 1024>>>(out);
}